// round 15
// baseline (speedup 1.0000x reference)
#include <cuda_runtime.h>
#include <cuda_bf16.h>
#include <cstdint>

#define BB 8
#define QQ 128
#define VV 512
#define HH 512

#define NQ (BB*QQ*HH)
#define NV (BB*VV*HH)

// ---------------------------------------------------------------------------
// Device scratch
// ---------------------------------------------------------------------------
__device__ float g_qp[NQ];
__device__ float g_vp[NV];         // COMPACT: per batch, slots [0,cnt) valid
__device__ float g_sc[BB*QQ*VV];   // compact exp-scores
__device__ int   g_idx[BB*VV];     // compacted unmasked v indices (pad 0)
__device__ int   g_cnt[BB];

// ---------------------------------------------------------------------------
// Fast transcendentals
// ---------------------------------------------------------------------------
__device__ __forceinline__ float fast_ex2(float x) {
    float y;
    asm("ex2.approx.ftz.f32 %0, %1;" : "=f"(y) : "f"(x));
    return y;
}
__device__ __forceinline__ float tanh_fast(float x) {
    float y;
    asm("tanh.approx.f32 %0, %1;" : "=f"(y) : "f"(x));
    return y;
}

// cp.async helpers
__device__ __forceinline__ void cp_async16(void* dst_smem, const void* src_gmem) {
    uint32_t d = (uint32_t)__cvta_generic_to_shared(dst_smem);
    asm volatile("cp.async.cg.shared.global [%0], [%1], 16;\n" :: "r"(d), "l"(src_gmem) : "memory");
}
__device__ __forceinline__ void cp_commit() {
    asm volatile("cp.async.commit_group;\n" ::: "memory");
}
__device__ __forceinline__ void cp_wait1() {
    asm volatile("cp.async.wait_group 1;\n" ::: "memory");
}
__device__ __forceinline__ void cp_wait0() {
    asm volatile("cp.async.wait_group 0;\n" ::: "memory");
}

// ldmatrix x4 (b16)
__device__ __forceinline__ void ldsm_x4(uint32_t* r, uint32_t addr) {
    asm volatile("ldmatrix.sync.aligned.m8n8.x4.shared.b16 {%0,%1,%2,%3}, [%4];"
        : "=r"(r[0]), "=r"(r[1]), "=r"(r[2]), "=r"(r[3]) : "r"(addr));
}

// ---------------------------------------------------------------------------
// K0: mask compaction. 8 blocks, 512 threads. Deterministic.
// ---------------------------------------------------------------------------
__global__ void compact_kernel(const int* __restrict__ mask) {
    __shared__ int wsum_s[16];
    __shared__ int wbase_s[16];
    __shared__ int tot_s;
    const int b = blockIdx.x;
    const int tid = threadIdx.x;
    const int m = mask[b * VV + tid];
    unsigned bal = __ballot_sync(0xffffffffu, m != 0);
    int lanep = __popc(bal & ((1u << (tid & 31)) - 1u));
    int wid = tid >> 5;
    if ((tid & 31) == 0) wsum_s[wid] = __popc(bal);
    __syncthreads();
    if (tid == 0) {
        int acc = 0;
        for (int i = 0; i < 16; i++) { wbase_s[i] = acc; acc += wsum_s[i]; }
        tot_s = acc;
        g_cnt[b] = acc;
    }
    __syncthreads();
    if (m) g_idx[b * VV + wbase_s[wid] + lanep] = tid;
    if (tid >= tot_s) g_idx[b * VV + tid] = 0;
}

// ---------------------------------------------------------------------------
// K2: merged projection GEMM (unchanged from R14; vp gathers + early exit)
// ---------------------------------------------------------------------------
#define GBM 128
#define GBN 64
#define GBK 64
#define GSTRIDE (GBK + 8)
#define QP_MTILES (BB*QQ/GBM)   // 8
#define VP_MTILES (BB*VV/GBM)   // 32

#define GEMM_SMEM_BF16 (2*GBM*GSTRIDE + 2*GBN*GSTRIDE)
#define GEMM_SMEM_BYTES (GEMM_SMEM_BF16 * 2)
#define ALO_B (GBM*GSTRIDE*2)
#define BLO_B (GBN*GSTRIDE*2)

__device__ __forceinline__ void mma16816(float* d, const uint32_t* a, const uint32_t* b) {
    asm volatile(
        "mma.sync.aligned.m16n8k16.row.col.f32.bf16.bf16.f32 "
        "{%0,%1,%2,%3}, {%4,%5,%6,%7}, {%8,%9}, {%0,%1,%2,%3};"
        : "+f"(d[0]), "+f"(d[1]), "+f"(d[2]), "+f"(d[3])
        : "r"(a[0]), "r"(a[1]), "r"(a[2]), "r"(a[3]), "r"(b[0]), "r"(b[1]));
}

__device__ __forceinline__ void split4(float4 v, uint2* hi, uint2* lo) {
    __nv_bfloat16 h0 = __float2bfloat16(v.x);
    __nv_bfloat16 h1 = __float2bfloat16(v.y);
    __nv_bfloat16 h2 = __float2bfloat16(v.z);
    __nv_bfloat16 h3 = __float2bfloat16(v.w);
    __nv_bfloat16 l0 = __float2bfloat16(v.x - __bfloat162float(h0));
    __nv_bfloat16 l1 = __float2bfloat16(v.y - __bfloat162float(h1));
    __nv_bfloat16 l2 = __float2bfloat16(v.z - __bfloat162float(h2));
    __nv_bfloat16 l3 = __float2bfloat16(v.w - __bfloat162float(h3));
    __nv_bfloat162 hA = {h0, h1}, hB = {h2, h3};
    __nv_bfloat162 lA = {l0, l1}, lB = {l2, l3};
    hi->x = *(uint32_t*)&hA; hi->y = *(uint32_t*)&hB;
    lo->x = *(uint32_t*)&lA; lo->y = *(uint32_t*)&lB;
}

__global__ __launch_bounds__(256, 2) void gemm_both_kernel(
    const float* __restrict__ query, const float* __restrict__ Wq,
    const float* __restrict__ bq,
    const float* __restrict__ values, const float* __restrict__ Wv,
    const float* __restrict__ bv) {
    const int K = HH;
    const int N = HH;
    extern __shared__ __nv_bfloat16 gsm[];
    __nv_bfloat16* As = gsm;
    __nv_bfloat16* Bs = gsm + 2 * GBM * GSTRIDE;

    const float *A, *B, *bias;
    float* C;
    int mt = blockIdx.x;
    const int tid = threadIdx.x;
    const int sr = tid >> 4;
    const int scc = (tid & 15) * 4;

    int m0;
    int arow[8];
    if (mt < QP_MTILES) {
        A = query; B = Wq; bias = bq; C = g_qp;
        m0 = mt * GBM;
#pragma unroll
        for (int i = 0; i < 8; i++) arow[i] = m0 + i * 16 + sr;
    } else {
        mt -= QP_MTILES;
        const int b = mt >> 2;
        const int slot0 = (mt & 3) * GBM;
        if (slot0 >= g_cnt[b]) return;
        A = values; B = Wv; bias = bv; C = g_vp;
        m0 = b * VV + slot0;
#pragma unroll
        for (int i = 0; i < 8; i++)
            arow[i] = b * VV + g_idx[b * VV + slot0 + i * 16 + sr];
    }
    const int n0 = blockIdx.y * GBN;
    const int wid = tid >> 5;
    const int lane = tid & 31;
    const int wm = (wid >> 1) * 32;
    const int wn = (wid & 1) * 32;
    const int gp = lane >> 2;
    const int tg = lane & 3;

    const uint32_t As_b = (uint32_t)__cvta_generic_to_shared(As);
    const uint32_t Bs_b = (uint32_t)__cvta_generic_to_shared(Bs);
    const uint32_t aoff = ((wm + (lane & 15)) * GSTRIDE + ((lane >> 4) * 8)) * 2;
    const uint32_t boff = ((wn + ((lane >> 4) & 1) * 8 + (lane & 7)) * GSTRIDE
                           + ((lane >> 3) & 1) * 8) * 2;

    float d[2][4][4];
#pragma unroll
    for (int mi = 0; mi < 2; mi++)
#pragma unroll
        for (int ni = 0; ni < 4; ni++)
#pragma unroll
            for (int r = 0; r < 4; r++) d[mi][ni][r] = 0.0f;

    float4 aReg[8], bReg[4];
#pragma unroll
    for (int i = 0; i < 8; i++)
        aReg[i] = *(const float4*)(A + (size_t)arow[i] * K + scc);
#pragma unroll
    for (int i = 0; i < 4; i++)
        bReg[i] = *(const float4*)(B + (size_t)(n0 + i * 16 + sr) * K + scc);

    for (int k0 = 0; k0 < K; k0 += GBK) {
#pragma unroll
        for (int i = 0; i < 8; i++) {
            uint2 hi, lo;
            split4(aReg[i], &hi, &lo);
            int r = i * 16 + sr;
            *(uint2*)(As + r * GSTRIDE + scc) = hi;
            *(uint2*)(As + GBM * GSTRIDE + r * GSTRIDE + scc) = lo;
        }
#pragma unroll
        for (int i = 0; i < 4; i++) {
            uint2 hi, lo;
            split4(bReg[i], &hi, &lo);
            int r = i * 16 + sr;
            *(uint2*)(Bs + r * GSTRIDE + scc) = hi;
            *(uint2*)(Bs + GBN * GSTRIDE + r * GSTRIDE + scc) = lo;
        }
        __syncthreads();

        if (k0 + GBK < K) {
            int kn = k0 + GBK;
#pragma unroll
            for (int i = 0; i < 8; i++)
                aReg[i] = *(const float4*)(A + (size_t)arow[i] * K + kn + scc);
#pragma unroll
            for (int i = 0; i < 4; i++)
                bReg[i] = *(const float4*)(B + (size_t)(n0 + i * 16 + sr) * K + kn + scc);
        }

#pragma unroll
        for (int ks = 0; ks < GBK; ks += 16) {
            const uint32_t kb = ks * 2;
            uint32_t ah[2][4], al[2][4], bh[2][4], bl[2][4];
            ldsm_x4(ah[0], As_b + aoff + kb);
            ldsm_x4(ah[1], As_b + aoff + 16 * GSTRIDE * 2 + kb);
            ldsm_x4(al[0], As_b + ALO_B + aoff + kb);
            ldsm_x4(al[1], As_b + ALO_B + aoff + 16 * GSTRIDE * 2 + kb);
            ldsm_x4(bh[0], Bs_b + boff + kb);
            ldsm_x4(bh[1], Bs_b + boff + 16 * GSTRIDE * 2 + kb);
            ldsm_x4(bl[0], Bs_b + BLO_B + boff + kb);
            ldsm_x4(bl[1], Bs_b + BLO_B + boff + 16 * GSTRIDE * 2 + kb);
#pragma unroll
            for (int mi = 0; mi < 2; mi++)
#pragma unroll
                for (int ni = 0; ni < 4; ni++)
                    mma16816(d[mi][ni], ah[mi], &bh[ni >> 1][(ni & 1) * 2]);
#pragma unroll
            for (int mi = 0; mi < 2; mi++)
#pragma unroll
                for (int ni = 0; ni < 4; ni++)
                    mma16816(d[mi][ni], ah[mi], &bl[ni >> 1][(ni & 1) * 2]);
#pragma unroll
            for (int mi = 0; mi < 2; mi++)
#pragma unroll
                for (int ni = 0; ni < 4; ni++)
                    mma16816(d[mi][ni], al[mi], &bh[ni >> 1][(ni & 1) * 2]);
        }
        __syncthreads();
    }

#pragma unroll
    for (int mi = 0; mi < 2; mi++)
#pragma unroll
        for (int ni = 0; ni < 4; ni++) {
            int r = m0 + wm + mi * 16 + gp;
            int c = n0 + wn + ni * 8 + tg * 2;
            float b0 = bias[c], b1 = bias[c + 1];
            float* Cp = C + (size_t)r * N + c;
            float2 v0 = make_float2(d[mi][ni][0] + b0, d[mi][ni][1] + b1);
            float2 v1 = make_float2(d[mi][ni][2] + b0, d[mi][ni][3] + b1);
            *(float2*)(Cp) = v0;
            *(float2*)(Cp + 8 * N) = v1;
        }
}

// ---------------------------------------------------------------------------
// K3a: score kernel (unchanged from R14).
// ---------------------------------------------------------------------------
#define AVT 16
#define ANT 4
#define HP (HH + 4)
#define A_SMEM_FLOATS (8*HP + HH + 2*AVT*HP)
#define A_SMEM_BYTES (A_SMEM_FLOATS*4)

__device__ __forceinline__ void load_tile16(float* dst, const float* src, int tid) {
#pragma unroll
    for (int i = 0; i < 8; i++) {
        int lin = i * 256 + tid;
        int r = lin >> 7;
        int c = (lin & 127) << 2;
        cp_async16(dst + r * HP + c, src + (size_t)r * HH + c);
    }
}

__global__ __launch_bounds__(256, 2) void score_kernel(
    const float* __restrict__ qp, const float* __restrict__ wc,
    const float* __restrict__ bc) {
    extern __shared__ float sma[];
    float* qp_s = sma;
    float* wc_s = qp_s + 8 * HP;
    float* buf = wc_s + HH;

    const int tid = threadIdx.x;
    const int bx = blockIdx.x;
    const int vc = bx & 7;
    const int qt = (bx >> 3) & 15;
    const int b = bx >> 7;
    const int q0 = qt * 8;
    const int v0 = vc * 64;

    const int cnt = g_cnt[b];
    if (v0 >= cnt) return;

    const float* vpb = g_vp + (size_t)(b * VV + v0) * HH;

    load_tile16(buf, vpb, tid);
    cp_commit();

#pragma unroll
    for (int i = 0; i < 4; i++) {
        int lin = i * 256 + tid;
        int r = lin >> 7, c = lin & 127;
        ((float4*)(qp_s + r * HP))[c] =
            ((const float4*)(qp + (size_t)(b * QQ + q0 + r) * HH))[c];
    }
    if (tid < 128) ((float4*)wc_s)[tid] = ((const float4*)wc)[tid];
    const float bcv = bc[0];

    const int q = tid >> 5;
    const int lane = tid & 31;
    const int hc = lane & 7;
    const int vg = lane >> 3;

    for (int t = 0; t < ANT; t++) {
        float* cur = buf + (t & 1) * AVT * HP;
        if (t + 1 < ANT) {
            load_tile16(buf + ((t + 1) & 1) * AVT * HP, vpb + (size_t)(t + 1) * AVT * HH, tid);
            cp_commit();
            cp_wait1();
        } else {
            cp_wait0();
        }
        __syncthreads();

        const float* qrow = qp_s + q * HP;
        const float* wrow = wc_s;
        const float* v0p = cur + (vg * 4 + 0) * HP;
        const float* v1p = cur + (vg * 4 + 1) * HP;
        const float* v2p = cur + (vg * 4 + 2) * HP;
        const float* v3p = cur + (vg * 4 + 3) * HP;
        float acc0 = 0.f, acc1 = 0.f, acc2 = 0.f, acc3 = 0.f;
#pragma unroll
        for (int i = 0; i < 16; i++) {
            int h = i * 32 + hc * 4;
            float4 a = *(const float4*)(qrow + h);
            float4 w = *(const float4*)(wrow + h);
            float4 c0 = *(const float4*)(v0p + h);
            float4 c1 = *(const float4*)(v1p + h);
            float4 c2 = *(const float4*)(v2p + h);
            float4 c3 = *(const float4*)(v3p + h);
            acc0 = fmaf(w.x, tanh_fast(a.x + c0.x), acc0);
            acc0 = fmaf(w.y, tanh_fast(a.y + c0.y), acc0);
            acc0 = fmaf(w.z, tanh_fast(a.z + c0.z), acc0);
            acc0 = fmaf(w.w, tanh_fast(a.w + c0.w), acc0);
            acc1 = fmaf(w.x, tanh_fast(a.x + c1.x), acc1);
            acc1 = fmaf(w.y, tanh_fast(a.y + c1.y), acc1);
            acc1 = fmaf(w.z, tanh_fast(a.z + c1.z), acc1);
            acc1 = fmaf(w.w, tanh_fast(a.w + c1.w), acc1);
            acc2 = fmaf(w.x, tanh_fast(a.x + c2.x), acc2);
            acc2 = fmaf(w.y, tanh_fast(a.y + c2.y), acc2);
            acc2 = fmaf(w.z, tanh_fast(a.z + c2.z), acc2);
            acc2 = fmaf(w.w, tanh_fast(a.w + c2.w), acc2);
            acc3 = fmaf(w.x, tanh_fast(a.x + c3.x), acc3);
            acc3 = fmaf(w.y, tanh_fast(a.y + c3.y), acc3);
            acc3 = fmaf(w.z, tanh_fast(a.z + c3.z), acc3);
            acc3 = fmaf(w.w, tanh_fast(a.w + c3.w), acc3);
        }
        acc0 += __shfl_xor_sync(0xffffffffu, acc0, 1);
        acc0 += __shfl_xor_sync(0xffffffffu, acc0, 2);
        acc0 += __shfl_xor_sync(0xffffffffu, acc0, 4);
        acc1 += __shfl_xor_sync(0xffffffffu, acc1, 1);
        acc1 += __shfl_xor_sync(0xffffffffu, acc1, 2);
        acc1 += __shfl_xor_sync(0xffffffffu, acc1, 4);
        acc2 += __shfl_xor_sync(0xffffffffu, acc2, 1);
        acc2 += __shfl_xor_sync(0xffffffffu, acc2, 2);
        acc2 += __shfl_xor_sync(0xffffffffu, acc2, 4);
        acc3 += __shfl_xor_sync(0xffffffffu, acc3, 1);
        acc3 += __shfl_xor_sync(0xffffffffu, acc3, 2);
        acc3 += __shfl_xor_sync(0xffffffffu, acc3, 4);
        if (hc < 4) {
            float myacc = (hc == 0) ? acc0 : (hc == 1) ? acc1 : (hc == 2) ? acc2 : acc3;
            int slot = v0 + t * AVT + vg * 4 + hc;
            if (slot < cnt) {
                float p = fast_ex2((myacc + bcv) * 1.4426950408889634f);
                g_sc[(size_t)(b * QQ + q0 + q) * VV + slot] = p;
            }
        }
        __syncthreads();
    }
}

// ---------------------------------------------------------------------------
// K3b: softmax + context, H-SPLIT: grid = 8b x 16qt x 2hh = 256 blocks,
// 512 threads, occ 2 -> one wave. Each block: 256 H columns for all 8 q;
// weights output rows hh*4..hh*4+3. Context thread = col(64 f4) x qpair(4)
// x vhalf(2); deterministic vh0+vh1 combine.
// ---------------------------------------------------------------------------
#define VT 32
#define VP (VV + 8)
#define HHH 256           // H columns per block
#define HPH (HHH + 4)     // padded stride (floats); 65 slots == 1 mod 8
#define B_SMEM_FLOATS (8*VP + 16 + 512 + 4096 + 2*VT*HPH)
#define B_SMEM_BYTES (B_SMEM_FLOATS*4)   // ~102 KB

__device__ __forceinline__ void load_tile32h(float* dst, const float* base,
                                             const int* idx, int hbase, int tid) {
#pragma unroll
    for (int i = 0; i < 4; i++) {          // 32 rows x 64 chunks = 2048 / 512
        int lin = i * 512 + tid;
        int r = lin >> 6;
        int c = (lin & 63) << 2;
        cp_async16(dst + r * HPH + c, base + (size_t)idx[r] * HH + hbase + c);
    }
}

__global__ __launch_bounds__(512, 2) void ctx_kernel(
    const float* __restrict__ values,
    float* __restrict__ out_ctx, float* __restrict__ out_w) {
    extern __shared__ float smb[];
    float* sc   = smb;                 // 8*VP
    float* wsum = sc + 8 * VP;         // 16
    int* idxs   = (int*)(wsum + 16);   // 512
    float* xb   = (float*)(idxs + 512);// 4096
    float* buf  = xb + 4096;           // 2*VT*HPH

    const int tid = threadIdx.x;
    const int hh = blockIdx.x & 1;
    const int qt = (blockIdx.x >> 1) & 15;
    const int b = blockIdx.x >> 5;
    const int q0 = qt * 8;
    const int hbase = hh * HHH;
    const int cnt = g_cnt[b];
    const int nt = (cnt + VT - 1) / VT;

    idxs[tid] = g_idx[b * VV + tid];
    __syncthreads();

    const float* valb = values + (size_t)b * VV * HH;

    load_tile32h(buf, valb, idxs, hbase, tid);
    cp_commit();

    // compact scores, zero-padded beyond cnt
#pragma unroll
    for (int i = 0; i < 8; i++) {
        int lin = i * 512 + tid;
        int r = lin >> 9, j = lin & 511;
        sc[r * VP + j] = (j < cnt) ?
            g_sc[(size_t)(b * QQ + q0 + r) * VV + j] : 0.0f;
    }
    __syncthreads();

    // deterministic row sums
    const int q = tid >> 6;
    const int vl = tid & 63;
    {
        float s = 0.0f;
#pragma unroll
        for (int j = 0; j < 8; j++) s += sc[q * VP + vl + 64 * j];
#pragma unroll
        for (int off = 16; off; off >>= 1) s += __shfl_down_sync(0xffffffffu, s, off);
        if ((tid & 31) == 0) wsum[tid >> 5] = s;
    }
    __syncthreads();
    const float inv = 1.0f / (wsum[2 * q] + wsum[2 * q + 1]);

    // normalize compact weights in smem
    {
#pragma unroll
        for (int j = 0; j < 8; j++) {
            int v = vl + 64 * j;
            sc[q * VP + v] *= inv;
        }
    }
    __syncthreads();

    // weights output: this block handles rows rbase..rbase+3
    const int rbase = hh * 4;
#pragma unroll
    for (int i = 0; i < 4; i++) xb[i * 512 + tid] = 0.0f;
    __syncthreads();
#pragma unroll
    for (int i = 0; i < 4; i++) {
        int lin = i * 512 + tid;
        int r = lin >> 9, j = lin & 511;
        if (j < cnt) xb[r * 512 + idxs[j]] = sc[(rbase + r) * VP + j];
    }
    __syncthreads();
#pragma unroll
    for (int i = 0; i < 4; i++) {
        int lin = i * 512 + tid;
        int r = lin >> 9, j = lin & 511;
        out_w[(size_t)(b * QQ + q0 + rbase + r) * VV + j] = xb[lin];
    }
    __syncthreads();

    // context: thread = col(64 f4) x qpair(4) x vhalf(2)
    const int ccol = tid & 63;
    const int cqp  = (tid >> 6) & 3;    // queries 2*cqp, 2*cqp+1
    const int cvh  = tid >> 8;          // v-half within tile
    float4 ca0 = make_float4(0.f,0.f,0.f,0.f);
    float4 ca1 = make_float4(0.f,0.f,0.f,0.f);

    for (int t = 0; t < nt; t++) {
        float* cur = buf + (t & 1) * VT * HPH;
        if (t + 1 < nt) {
            load_tile32h(buf + ((t + 1) & 1) * VT * HPH, valb, idxs + (t + 1) * VT, hbase, tid);
            cp_commit();
            cp_wait1();
        } else {
            cp_wait0();
        }
        __syncthreads();

        const float* wq0 = sc + (2 * cqp + 0) * VP + t * VT + cvh * 16;
        const float* wq1 = sc + (2 * cqp + 1) * VP + t * VT + cvh * 16;
        const float* cb = cur + cvh * 16 * HPH;
#pragma unroll
        for (int v = 0; v < 16; v++) {
            float4 c = ((const float4*)(cb + v * HPH))[ccol];
            float w0 = wq0[v], w1 = wq1[v];
            ca0.x = fmaf(w0, c.x, ca0.x); ca0.y = fmaf(w0, c.y, ca0.y);
            ca0.z = fmaf(w0, c.z, ca0.z); ca0.w = fmaf(w0, c.w, ca0.w);
            ca1.x = fmaf(w1, c.x, ca1.x); ca1.y = fmaf(w1, c.y, ca1.y);
            ca1.z = fmaf(w1, c.z, ca1.z); ca1.w = fmaf(w1, c.w, ca1.w);
        }
        __syncthreads();
    }

    // combine v-halves (deterministic: vh0 + vh1) and write out
    float4* xbv = (float4*)xb;
    const int xi = (cqp * 64 + ccol) * 2;
    if (cvh == 1) {
        xbv[xi + 0] = ca0; xbv[xi + 1] = ca1;
    }
    __syncthreads();
    if (cvh == 0) {
        float4 p0 = xbv[xi + 0], p1 = xbv[xi + 1];
        ca0.x += p0.x; ca0.y += p0.y; ca0.z += p0.z; ca0.w += p0.w;
        ca1.x += p1.x; ca1.y += p1.y; ca1.z += p1.z; ca1.w += p1.w;
        float* oc = out_ctx + (size_t)(b * QQ + q0 + 2 * cqp) * HH + hbase;
        ((float4*)oc)[ccol] = ca0;
        ((float4*)(oc + HH))[ccol] = ca1;
    }
}

// ---------------------------------------------------------------------------
// Launch
// ---------------------------------------------------------------------------
extern "C" void kernel_launch(void* const* d_in, const int* in_sizes, int n_in,
                              void* d_out, int out_size) {
    const float* query  = (const float*)d_in[0];
    const float* values = (const float*)d_in[1];
    const int*   mask   = (const int*)d_in[2];
    const float* Wq     = (const float*)d_in[3];
    const float* bq     = (const float*)d_in[4];
    const float* Wv     = (const float*)d_in[5];
    const float* bv     = (const float*)d_in[6];
    const float* wc     = (const float*)d_in[7];
    const float* bc     = (const float*)d_in[8];

    float* out_ctx = (float*)d_out;
    float* out_w   = (float*)d_out + (size_t)BB * QQ * HH;

    void *qp;
    cudaGetSymbolAddress(&qp, g_qp);

    // K0: mask compaction
    compact_kernel<<<BB, 512>>>(mask);

    // K2: projections; vp tiles gather unmasked rows and early-exit beyond cnt
    cudaFuncSetAttribute(gemm_both_kernel, cudaFuncAttributeMaxDynamicSharedMemorySize, GEMM_SMEM_BYTES);
    dim3 gboth(QP_MTILES + VP_MTILES, HH / GBN);
    gemm_both_kernel<<<gboth, 256, GEMM_SMEM_BYTES>>>(query, Wq, bq, values, Wv, bv);

    // K3a: scores over compact slots
    cudaFuncSetAttribute(score_kernel, cudaFuncAttributeMaxDynamicSharedMemorySize, A_SMEM_BYTES);
    score_kernel<<<1024, 256, A_SMEM_BYTES>>>((const float*)qp, wc, bc);

    // K3b: softmax + context, H-split (256 blocks, one wave)
    cudaFuncSetAttribute(ctx_kernel, cudaFuncAttributeMaxDynamicSharedMemorySize, B_SMEM_BYTES);
    ctx_kernel<<<BB * 16 * 2, 512, B_SMEM_BYTES>>>(values, out_ctx, out_w);
}